// round 16
// baseline (speedup 1.0000x reference)
#include <cuda_runtime.h>
#include <cuda_fp16.h>
#include <math_constants.h>
#include <cstdint>

#define Bsz  8
#define Nseq 1024
#define Cdim 1024
#define Hn   16
#define Dh   64
#define Mrows (Bsz * Nseq)
#define OQKV 3072

// ---------------------------------------------------------------------------
// Device-global scratch (allocation-free rule) — all single fp16
// ---------------------------------------------------------------------------
__device__ __half g_x16[Mrows * Cdim];         // x
__device__ __half g_wq [OQKV * Cdim];          // w_qkv
__device__ __half g_wp [Cdim * Cdim];          // w_proj
__device__ __half g_ao [Mrows * Cdim];         // attention out
__device__ __half g_q  [Bsz * Hn * Nseq * Dh]; // q (pre-scaled)
__device__ __half g_k  [Bsz * Hn * Nseq * Dh];
__device__ __half g_v  [Bsz * Hn * Nseq * Dh];

// ---------------------------------------------------------------------------
// PTX helpers
// ---------------------------------------------------------------------------
__device__ __forceinline__ uint32_t s2u(const void* p) {
    uint32_t a;
    asm("{ .reg .u64 t; cvta.to.shared.u64 t, %1; cvt.u32.u64 %0, t; }"
        : "=r"(a) : "l"(p));
    return a;
}

__device__ __forceinline__ void ldsm4(uint32_t* r, uint32_t addr) {
    asm volatile("ldmatrix.sync.aligned.m8n8.x4.shared.b16 {%0,%1,%2,%3}, [%4];"
                 : "=r"(r[0]), "=r"(r[1]), "=r"(r[2]), "=r"(r[3]) : "r"(addr));
}

__device__ __forceinline__ void ldsm4t(uint32_t* r, uint32_t addr) {
    asm volatile("ldmatrix.sync.aligned.m8n8.x4.trans.shared.b16 {%0,%1,%2,%3}, [%4];"
                 : "=r"(r[0]), "=r"(r[1]), "=r"(r[2]), "=r"(r[3]) : "r"(addr));
}

__device__ __forceinline__ void mma16816h(float* c, const uint32_t* a,
                                          const uint32_t* b) {
    asm volatile(
        "mma.sync.aligned.m16n8k16.row.col.f32.f16.f16.f32 "
        "{%0,%1,%2,%3}, {%4,%5,%6,%7}, {%8,%9}, {%0,%1,%2,%3};"
        : "+f"(c[0]), "+f"(c[1]), "+f"(c[2]), "+f"(c[3])
        : "r"(a[0]), "r"(a[1]), "r"(a[2]), "r"(a[3]), "r"(b[0]), "r"(b[1]));
}

__device__ __forceinline__ void cpa16(uint32_t saddr, const void* g) {
    asm volatile("cp.async.cg.shared.global [%0], [%1], 16;"
                 :: "r"(saddr), "l"(g));
}
#define CP_COMMIT asm volatile("cp.async.commit_group;")
#define CP_WAIT(n) asm volatile("cp.async.wait_group %0;" :: "n"(n))

__device__ __forceinline__ float ex2(float x) {
    float r;
    asm("ex2.approx.ftz.f32 %0, %1;" : "=f"(r) : "f"(x));
    return r;
}

__device__ __forceinline__ uint32_t packh2(float a, float b) {
    __half2 p = __floats2half2_rn(a, b);
    return reinterpret_cast<uint32_t&>(p);
}

// ---------------------------------------------------------------------------
// Conversion pre-pass: everything -> single fp16 (one merged launch)
// ---------------------------------------------------------------------------
#define X4  ((Mrows * Cdim) / 4)
#define WQ4 ((OQKV * Cdim) / 4)
#define WP4 ((Cdim * Cdim) / 4)

__global__ __launch_bounds__(256) void cvt_all(const float4* __restrict__ x,
                                               const float4* __restrict__ wq,
                                               const float4* __restrict__ wp) {
    int i = blockIdx.x * blockDim.x + threadIdx.x;
    const float4* in;
    __half* dst;
    int j;
    if (i < X4)                  { in = x;  dst = g_x16; j = i; }
    else if (i < X4 + WQ4)       { in = wq; dst = g_wq;  j = i - X4; }
    else if (i < X4 + WQ4 + WP4) { in = wp; dst = g_wp;  j = i - X4 - WQ4; }
    else return;
    float4 v = in[j];
    uint2 H;
    H.x = packh2(v.x, v.y);
    H.y = packh2(v.z, v.w);
    ((uint2*)dst)[j] = H;
}

// ---------------------------------------------------------------------------
// fp16 single-pass GEMM (R13 structure, deeper pipeline):
// CTA 128x128, 8 warps (64x32), KC=64, 4-stage cp.async, refill at chunk TOP
// (target stage (c+3)%4 == (c-1)%4 — reads done before this chunk's barrier),
// CP_WAIT(2) -> 2 groups always in flight. Frag ks ping-pong in registers.
// mode 0: scatter q/k/v fp16 (q pre-scaled);  mode 1: +bias -> fp32 out.
// ---------------------------------------------------------------------------
#define KC    64
#define PITCH 144                      // 128B data + 16B pad, ldsm conflict-free
#define REGB  (128 * PITCH)            // 18432
#define GBUFB (2 * REGB)               // A, B = 36864 per stage
#define NSTAGE 4
#define GEMM_SMEM (NSTAGE * GBUFB)     // 147456

__global__ __launch_bounds__(256, 1) void gemm_f16(int mode,
                                                   const float* __restrict__ bias,
                                                   float* __restrict__ out) {
    extern __shared__ char smem[];
    const uint32_t sb = s2u(smem);
    const int tid = threadIdx.x;
    const int m0 = blockIdx.y * 128;
    const int o0 = blockIdx.x * 128;

    const __half* srcs[2] = {
        ((mode == 0) ? g_x16 : g_ao) + (size_t)m0 * Cdim,
        ((mode == 0) ? g_wq  : g_wp) + (size_t)o0 * Cdim};

    auto issue = [&](int c, int stage) {
        uint32_t s0 = sb + stage * GBUFB;
        const int ko = c * KC;
#pragma unroll
        for (int j = 0; j < 8; j++) {
            int idx = j * 256 + tid;      // 0..2047
            int mt  = idx >> 10;
            int r   = (idx >> 3) & 127;
            int c8  = idx & 7;
            cpa16(s0 + mt * REGB + r * PITCH + c8 * 16,
                  srcs[mt] + r * Cdim + ko + c8 * 8);
        }
    };

    const int wid = tid >> 5, lane = tid & 31;
    const int wm = wid >> 2;
    const int wn = wid & 3;

    const int a_row  = wm * 64 + (lane & 15);
    const int a_colb = (lane >> 4) * 16;
    const int b_row  = wn * 32 + ((lane >> 4) << 3) + (lane & 7);
    const int b_colb = ((lane >> 3) & 1) * 16;

    float acc[4][4][4];
#pragma unroll
    for (int i = 0; i < 4; i++)
#pragma unroll
        for (int j = 0; j < 4; j++)
#pragma unroll
            for (int k = 0; k < 4; k++) acc[i][j][k] = 0.0f;

    issue(0, 0); CP_COMMIT;
    issue(1, 1); CP_COMMIT;
    issue(2, 2); CP_COMMIT;

    uint32_t Af[2][4][4], Bf[2][2][4];

    auto loadfrags = [&](int buf, uint32_t base, int ks) {
#pragma unroll
        for (int mb = 0; mb < 4; mb++)
            ldsm4(Af[buf][mb],
                  base + (a_row + mb * 16) * PITCH + ks * 32 + a_colb);
#pragma unroll
        for (int nbp = 0; nbp < 2; nbp++)
            ldsm4(Bf[buf][nbp],
                  base + REGB + (b_row + nbp * 16) * PITCH + ks * 32 + b_colb);
    };
    auto do_mma = [&](int buf) {
#pragma unroll
        for (int mb = 0; mb < 4; mb++)
#pragma unroll
            for (int nb = 0; nb < 4; nb++)
                mma16816h(acc[mb][nb], Af[buf][mb],
                          &Bf[buf][nb >> 1][(nb & 1) * 2]);
    };

    const int NCH = Cdim / KC;   // 16
    for (int c = 0; c < NCH; c++) {
        if (c + 2 < NCH)      { CP_WAIT(2); }
        else if (c + 1 < NCH) { CP_WAIT(1); }
        else                  { CP_WAIT(0); }
        __syncthreads();
        // refill at TOP: stage (c+3)&3 == (c-1)&3, reads finished before the
        // barrier above -> copy gets ~3 chunks to complete.
        if (c + 3 < NCH) { issue(c + 3, (c + 3) & 3); CP_COMMIT; }

        const uint32_t base = sb + (c & 3) * GBUFB;
        loadfrags(0, base, 0);
#pragma unroll
        for (int ks = 0; ks < 4; ks++) {
            const int cur = ks & 1;
            if (ks < 3) loadfrags(cur ^ 1, base, ks + 1);
            do_mma(cur);
        }
    }

    const int erow = m0 + wm * 64 + (lane >> 2);
    const int ecol = o0 + wn * 32 + (lane & 3) * 2;
    if (mode == 0) {
        const int which = o0 >> 10;     // 0=q 1=k 2=v
        const float qs = 0.125f * 1.44269504088896340736f;
        __half* dstb = (which == 0) ? g_q : (which == 1) ? g_k : g_v;
        const float sc = (which == 0) ? qs : 1.0f;
#pragma unroll
        for (int mb = 0; mb < 4; mb++) {
            const int m = erow + mb * 16;
            const int bb = m >> 10, n = m & 1023;
#pragma unroll
            for (int nb = 0; nb < 4; nb++) {
                const int o = ecol + nb * 8;
                const int h = (o & 1023) >> 6;
                const int d = o & 63;
                size_t base = ((size_t)(bb * Hn + h) * Nseq + n) * Dh + d;
                *(uint32_t*)(dstb + base)          = packh2(acc[mb][nb][0] * sc,
                                                            acc[mb][nb][1] * sc);
                *(uint32_t*)(dstb + base + 8 * Dh) = packh2(acc[mb][nb][2] * sc,
                                                            acc[mb][nb][3] * sc);
            }
        }
    } else {
#pragma unroll
        for (int mb = 0; mb < 4; mb++) {
            const int m = erow + mb * 16;
#pragma unroll
            for (int nb = 0; nb < 4; nb++) {
                const int o = ecol + nb * 8;
                const float2 bv = *(const float2*)(bias + o);
                float* dst = out + (size_t)m * Cdim + o;
                *(float2*)dst = make_float2(acc[mb][nb][0] + bv.x,
                                            acc[mb][nb][1] + bv.y);
                *(float2*)(dst + 8 * Cdim) = make_float2(acc[mb][nb][2] + bv.x,
                                                         acc[mb][nb][3] + bv.y);
            }
        }
    }
}

// ---------------------------------------------------------------------------
// Flash attention, single fp16: S = Q*K^T, O += P*V.
// CTA: 128 Q rows x one (b,h), 8 warps. KV in 64-row tiles, 3-stage ring,
// refill at chunk TOP (stage (kb+2)%3 = (kb-1)%3 — reads done before this
// chunk's barrier), no trailing barrier. smem 74KB -> 2 CTAs/SM.
// ---------------------------------------------------------------------------
#define APITCH 144
#define AQREG  (128 * APITCH)            // 18432 (one Q matrix)
#define AKREG  (64 * APITCH)             // 9216 per KV matrix
#define AKV0   AQREG
#define ASTAGE (2 * AKREG)               // K, V = 18432
#define ANST   3
#define ATTN_SMEM (AQREG + ANST * ASTAGE)   // 73728

__global__ __launch_bounds__(256, 2) void attn_f16() {
    extern __shared__ char smem[];
    const uint32_t sb = s2u(smem);
    const int tid = threadIdx.x;
    const int w = tid >> 5, lane = tid & 31;
    const int bh = blockIdx.x;
    const int qb = blockIdx.y;

    const size_t hoff = (size_t)bh * (Nseq * Dh);
    const __half* qp = g_q + hoff + (size_t)qb * 128 * Dh;

    auto loadQ = [&]() {
#pragma unroll
        for (int j = 0; j < 4; j++) {
            int idx = j * 256 + tid;          // 0..1023
            int r   = (idx >> 3) & 127;
            int c8  = idx & 7;
            cpa16(sb + r * APITCH + c8 * 16, qp + r * Dh + c8 * 8);
        }
    };
    auto loadKV = [&](int kb, int st) {     // kb: 64-row block 0..15
        const size_t koff = hoff + (size_t)kb * 64 * Dh;
        const __half* srcs[2] = {g_k + koff, g_v + koff};
        uint32_t base = sb + AKV0 + st * ASTAGE;
#pragma unroll
        for (int j = 0; j < 4; j++) {
            int idx = j * 256 + tid;          // 0..1023
            int mt  = idx >> 9;               // 0=K 1=V
            int r   = (idx >> 3) & 63;
            int c8  = idx & 7;
            cpa16(base + mt * AKREG + r * APITCH + c8 * 16,
                  srcs[mt] + r * Dh + c8 * 8);
        }
    };

    loadQ();          CP_COMMIT;   // g0: Q
    loadKV(0, 0);     CP_COMMIT;   // g1: KV0
    loadKV(1, 1);     CP_COMMIT;   // g2: KV1

    const int a_rowb = (w * 16 + (lane & 15)) * APITCH + (lane >> 4) * 16;
    const int k_rowi = ((lane >> 4) << 3) + (lane & 7);
    const int k_colb = ((lane >> 3) & 1) * 16;
    const int v_rowi = (lane & 7) + ((lane >> 3) & 1) * 8;
    const int v_colb = (lane >> 4) * 16;

    CP_WAIT(2);       // Q resident
    __syncthreads();

    uint32_t QA[4][4];
#pragma unroll
    for (int kc = 0; kc < 4; kc++)
        ldsm4(QA[kc], sb + a_rowb + kc * 32);

    float O[8][4];
#pragma unroll
    for (int i = 0; i < 8; i++)
#pragma unroll
        for (int j = 0; j < 4; j++) O[i][j] = 0.0f;
    float m0 = -1e30f, m1 = -1e30f;
    float l0 = 0.0f, l1 = 0.0f;

    for (int kb = 0; kb < 16; kb++) {
        if (kb + 1 < 16) { CP_WAIT(1); } else { CP_WAIT(0); }
        __syncthreads();
        // refill at TOP: stage (kb+2)%3 = (kb-1)%3, reads finished before the
        // barrier above.
        if (kb + 2 < 16) { loadKV(kb + 2, (kb + 2) % ANST); CP_COMMIT; }

        const uint32_t kbase = sb + AKV0 + (kb % ANST) * ASTAGE;

        float S[8][4];
#pragma unroll
        for (int i = 0; i < 8; i++)
#pragma unroll
            for (int j = 0; j < 4; j++) S[i][j] = 0.0f;

#pragma unroll
        for (int ng = 0; ng < 4; ng++) {
#pragma unroll
            for (int kc = 0; kc < 4; kc++) {
                uint32_t kf[4];
                ldsm4(kf, kbase + (ng * 16 + k_rowi) * APITCH + k_colb + kc * 32);
#pragma unroll
                for (int half = 0; half < 2; half++)
                    mma16816h(S[ng * 2 + half], QA[kc], &kf[half * 2]);
            }
        }

        float rm0 = -1e30f, rm1 = -1e30f;
#pragma unroll
        for (int i = 0; i < 8; i++) {
            rm0 = fmaxf(rm0, fmaxf(S[i][0], S[i][1]));
            rm1 = fmaxf(rm1, fmaxf(S[i][2], S[i][3]));
        }
        rm0 = fmaxf(rm0, __shfl_xor_sync(0xffffffffu, rm0, 1));
        rm0 = fmaxf(rm0, __shfl_xor_sync(0xffffffffu, rm0, 2));
        rm1 = fmaxf(rm1, __shfl_xor_sync(0xffffffffu, rm1, 1));
        rm1 = fmaxf(rm1, __shfl_xor_sync(0xffffffffu, rm1, 2));

        float mn0 = fmaxf(m0, rm0), mn1 = fmaxf(m1, rm1);
        float al0 = ex2(m0 - mn0),  al1 = ex2(m1 - mn1);
        m0 = mn0; m1 = mn1;
        l0 *= al0; l1 *= al1;
#pragma unroll
        for (int i = 0; i < 8; i++) {
            O[i][0] *= al0; O[i][1] *= al0;
            O[i][2] *= al1; O[i][3] *= al1;
        }
        float ps0 = 0.0f, ps1 = 0.0f;
#pragma unroll
        for (int i = 0; i < 8; i++) {
            S[i][0] = ex2(S[i][0] - mn0);
            S[i][1] = ex2(S[i][1] - mn0);
            S[i][2] = ex2(S[i][2] - mn1);
            S[i][3] = ex2(S[i][3] - mn1);
            ps0 += S[i][0] + S[i][1];
            ps1 += S[i][2] + S[i][3];
        }
        l0 += ps0; l1 += ps1;

#pragma unroll
        for (int kc2 = 0; kc2 < 4; kc2++) {
            uint32_t pf[4];
            pf[0] = packh2(S[2 * kc2][0],     S[2 * kc2][1]);
            pf[1] = packh2(S[2 * kc2][2],     S[2 * kc2][3]);
            pf[2] = packh2(S[2 * kc2 + 1][0], S[2 * kc2 + 1][1]);
            pf[3] = packh2(S[2 * kc2 + 1][2], S[2 * kc2 + 1][3]);
#pragma unroll
            for (int dg = 0; dg < 4; dg++) {
                uint32_t vf[4];
                ldsm4t(vf, kbase + AKREG
                           + (kc2 * 16 + v_rowi) * APITCH + v_colb + dg * 32);
#pragma unroll
                for (int half = 0; half < 2; half++)
                    mma16816h(O[dg * 2 + half], pf, &vf[half * 2]);
            }
        }
    }

    l0 += __shfl_xor_sync(0xffffffffu, l0, 1);
    l0 += __shfl_xor_sync(0xffffffffu, l0, 2);
    l1 += __shfl_xor_sync(0xffffffffu, l1, 1);
    l1 += __shfl_xor_sync(0xffffffffu, l1, 2);
    const float inv0 = 1.0f / l0, inv1 = 1.0f / l1;

    const int b = bh >> 4, h = bh & 15;
    const int n0 = qb * 128 + w * 16 + (lane >> 2);
#pragma unroll
    for (int nb = 0; nb < 8; nb++) {
        const int d = nb * 8 + (lane & 3) * 2;
        size_t base0 = ((size_t)(b * Nseq + n0) * Cdim) + h * Dh + d;
        size_t base1 = base0 + (size_t)8 * Cdim;
        *(uint32_t*)(g_ao + base0) = packh2(O[nb][0] * inv0, O[nb][1] * inv0);
        *(uint32_t*)(g_ao + base1) = packh2(O[nb][2] * inv1, O[nb][3] * inv1);
    }
}

// ---------------------------------------------------------------------------
extern "C" void kernel_launch(void* const* d_in, const int* in_sizes, int n_in,
                              void* d_out, int out_size) {
    const float* x      = (const float*)d_in[0];   // [8,1024,1024]
    const float* w_qkv  = (const float*)d_in[1];   // [3072,1024]
    const float* w_proj = (const float*)d_in[2];   // [1024,1024]
    const float* b_proj = (const float*)d_in[3];   // [1024]
    float* out = (float*)d_out;

    cudaFuncSetAttribute(gemm_f16,
                         cudaFuncAttributeMaxDynamicSharedMemorySize, GEMM_SMEM);
    cudaFuncSetAttribute(attn_f16,
                         cudaFuncAttributeMaxDynamicSharedMemorySize, ATTN_SMEM);

    {
        int n4 = X4 + WQ4 + WP4;
        cvt_all<<<(n4 + 255) / 256, 256>>>((const float4*)x,
                                           (const float4*)w_qkv,
                                           (const float4*)w_proj);
    }

    dim3 g1(OQKV / 128, Mrows / 128);              // (24, 64)
    gemm_f16<<<g1, 256, GEMM_SMEM>>>(0, nullptr, nullptr);

    dim3 g2(Bsz * Hn, Nseq / 128);                 // (128, 8)
    attn_f16<<<g2, 256, ATTN_SMEM>>>();

    dim3 g3(Cdim / 128, Mrows / 128);              // (8, 64)
    gemm_f16<<<g3, 256, GEMM_SMEM>>>(1, b_proj, out);
}

// round 17
// speedup vs baseline: 1.0821x; 1.0821x over previous
#include <cuda_runtime.h>
#include <cuda_fp16.h>
#include <math_constants.h>
#include <cstdint>

#define Bsz  8
#define Nseq 1024
#define Cdim 1024
#define Hn   16
#define Dh   64
#define Mrows (Bsz * Nseq)
#define OQKV 3072

// ---------------------------------------------------------------------------
// Device-global scratch (allocation-free rule) — all single fp16
// ---------------------------------------------------------------------------
__device__ __half g_x16[Mrows * Cdim];         // x
__device__ __half g_wq [OQKV * Cdim];          // w_qkv
__device__ __half g_wp [Cdim * Cdim];          // w_proj
__device__ __half g_ao [Mrows * Cdim];         // attention out
__device__ __half g_q  [Bsz * Hn * Nseq * Dh]; // q (pre-scaled)
__device__ __half g_k  [Bsz * Hn * Nseq * Dh];
__device__ __half g_v  [Bsz * Hn * Nseq * Dh];

// ---------------------------------------------------------------------------
// PTX helpers
// ---------------------------------------------------------------------------
__device__ __forceinline__ uint32_t s2u(const void* p) {
    uint32_t a;
    asm("{ .reg .u64 t; cvta.to.shared.u64 t, %1; cvt.u32.u64 %0, t; }"
        : "=r"(a) : "l"(p));
    return a;
}

__device__ __forceinline__ void ldsm4(uint32_t* r, uint32_t addr) {
    asm volatile("ldmatrix.sync.aligned.m8n8.x4.shared.b16 {%0,%1,%2,%3}, [%4];"
                 : "=r"(r[0]), "=r"(r[1]), "=r"(r[2]), "=r"(r[3]) : "r"(addr));
}

__device__ __forceinline__ void ldsm4t(uint32_t* r, uint32_t addr) {
    asm volatile("ldmatrix.sync.aligned.m8n8.x4.trans.shared.b16 {%0,%1,%2,%3}, [%4];"
                 : "=r"(r[0]), "=r"(r[1]), "=r"(r[2]), "=r"(r[3]) : "r"(addr));
}

__device__ __forceinline__ void mma16816h(float* c, const uint32_t* a,
                                          const uint32_t* b) {
    asm volatile(
        "mma.sync.aligned.m16n8k16.row.col.f32.f16.f16.f32 "
        "{%0,%1,%2,%3}, {%4,%5,%6,%7}, {%8,%9}, {%0,%1,%2,%3};"
        : "+f"(c[0]), "+f"(c[1]), "+f"(c[2]), "+f"(c[3])
        : "r"(a[0]), "r"(a[1]), "r"(a[2]), "r"(a[3]), "r"(b[0]), "r"(b[1]));
}

__device__ __forceinline__ void cpa16(uint32_t saddr, const void* g) {
    asm volatile("cp.async.cg.shared.global [%0], [%1], 16;"
                 :: "r"(saddr), "l"(g));
}
#define CP_COMMIT asm volatile("cp.async.commit_group;")
#define CP_WAIT(n) asm volatile("cp.async.wait_group %0;" :: "n"(n))

__device__ __forceinline__ float ex2(float x) {
    float r;
    asm("ex2.approx.ftz.f32 %0, %1;" : "=f"(r) : "f"(x));
    return r;
}

__device__ __forceinline__ uint32_t packh2(float a, float b) {
    __half2 p = __floats2half2_rn(a, b);
    return reinterpret_cast<uint32_t&>(p);
}

// ---------------------------------------------------------------------------
// Conversion pre-pass: everything -> single fp16 (one merged launch)
// ---------------------------------------------------------------------------
#define X4  ((Mrows * Cdim) / 4)
#define WQ4 ((OQKV * Cdim) / 4)
#define WP4 ((Cdim * Cdim) / 4)

__global__ __launch_bounds__(256) void cvt_all(const float4* __restrict__ x,
                                               const float4* __restrict__ wq,
                                               const float4* __restrict__ wp) {
    int i = blockIdx.x * blockDim.x + threadIdx.x;
    const float4* in;
    __half* dst;
    int j;
    if (i < X4)                  { in = x;  dst = g_x16; j = i; }
    else if (i < X4 + WQ4)       { in = wq; dst = g_wq;  j = i - X4; }
    else if (i < X4 + WQ4 + WP4) { in = wp; dst = g_wp;  j = i - X4 - WQ4; }
    else return;
    float4 v = in[j];
    uint2 H;
    H.x = packh2(v.x, v.y);
    H.y = packh2(v.z, v.w);
    ((uint2*)dst)[j] = H;
}

// ---------------------------------------------------------------------------
// fp16 single-pass GEMM (R13 config — best measured):
// CTA 128x128, 8 warps (64x32), KC=64 (4 ks sub-steps), 3-stage cp.async,
// 1 CTA/SM, frag ks ping-pong in registers, bottom refill.
// mode 0: scatter q/k/v fp16 (q pre-scaled);  mode 1: +bias -> fp32 out.
// ---------------------------------------------------------------------------
#define KC    64
#define PITCH 144                      // 128B data + 16B pad, ldsm conflict-free
#define REGB  (128 * PITCH)            // 18432
#define GBUFB (2 * REGB)               // A, B = 36864 per stage
#define NSTAGE 3
#define GEMM_SMEM (NSTAGE * GBUFB)     // 110592

__global__ __launch_bounds__(256, 1) void gemm_f16(int mode,
                                                   const float* __restrict__ bias,
                                                   float* __restrict__ out) {
    extern __shared__ char smem[];
    const uint32_t sb = s2u(smem);
    const int tid = threadIdx.x;
    const int m0 = blockIdx.y * 128;
    const int o0 = blockIdx.x * 128;

    const __half* srcs[2] = {
        ((mode == 0) ? g_x16 : g_ao) + (size_t)m0 * Cdim,
        ((mode == 0) ? g_wq  : g_wp) + (size_t)o0 * Cdim};

    auto issue = [&](int c, int stage) {
        uint32_t s0 = sb + stage * GBUFB;
        const int ko = c * KC;
#pragma unroll
        for (int j = 0; j < 8; j++) {
            int idx = j * 256 + tid;      // 0..2047
            int mt  = idx >> 10;
            int r   = (idx >> 3) & 127;
            int c8  = idx & 7;
            cpa16(s0 + mt * REGB + r * PITCH + c8 * 16,
                  srcs[mt] + r * Cdim + ko + c8 * 8);
        }
    };

    const int wid = tid >> 5, lane = tid & 31;
    const int wm = wid >> 2;
    const int wn = wid & 3;

    const int a_row  = wm * 64 + (lane & 15);
    const int a_colb = (lane >> 4) * 16;
    const int b_row  = wn * 32 + ((lane >> 4) << 3) + (lane & 7);
    const int b_colb = ((lane >> 3) & 1) * 16;

    float acc[4][4][4];
#pragma unroll
    for (int i = 0; i < 4; i++)
#pragma unroll
        for (int j = 0; j < 4; j++)
#pragma unroll
            for (int k = 0; k < 4; k++) acc[i][j][k] = 0.0f;

    issue(0, 0); CP_COMMIT;
    issue(1, 1); CP_COMMIT;

    uint32_t Af[2][4][4], Bf[2][2][4];

    auto loadfrags = [&](int buf, uint32_t base, int ks) {
#pragma unroll
        for (int mb = 0; mb < 4; mb++)
            ldsm4(Af[buf][mb],
                  base + (a_row + mb * 16) * PITCH + ks * 32 + a_colb);
#pragma unroll
        for (int nbp = 0; nbp < 2; nbp++)
            ldsm4(Bf[buf][nbp],
                  base + REGB + (b_row + nbp * 16) * PITCH + ks * 32 + b_colb);
    };
    auto do_mma = [&](int buf) {
#pragma unroll
        for (int mb = 0; mb < 4; mb++)
#pragma unroll
            for (int nb = 0; nb < 4; nb++)
                mma16816h(acc[mb][nb], Af[buf][mb],
                          &Bf[buf][nb >> 1][(nb & 1) * 2]);
    };

    const int NCH = Cdim / KC;   // 16
    for (int c = 0; c < NCH; c++) {
        if (c + 1 < NCH) { CP_WAIT(1); } else { CP_WAIT(0); }
        __syncthreads();

        const uint32_t base = sb + (c % NSTAGE) * GBUFB;
        loadfrags(0, base, 0);
#pragma unroll
        for (int ks = 0; ks < 4; ks++) {
            const int cur = ks & 1;
            if (ks < 3) loadfrags(cur ^ 1, base, ks + 1);
            do_mma(cur);
        }
        // stage (c+2)%3 == (c-1)%3: reads finished before this chunk's barrier.
        if (c + 2 < NCH) { issue(c + 2, (c + 2) % NSTAGE); CP_COMMIT; }
    }

    const int erow = m0 + wm * 64 + (lane >> 2);
    const int ecol = o0 + wn * 32 + (lane & 3) * 2;
    if (mode == 0) {
        const int which = o0 >> 10;     // 0=q 1=k 2=v
        const float qs = 0.125f * 1.44269504088896340736f;
        __half* dstb = (which == 0) ? g_q : (which == 1) ? g_k : g_v;
        const float sc = (which == 0) ? qs : 1.0f;
#pragma unroll
        for (int mb = 0; mb < 4; mb++) {
            const int m = erow + mb * 16;
            const int bb = m >> 10, n = m & 1023;
#pragma unroll
            for (int nb = 0; nb < 4; nb++) {
                const int o = ecol + nb * 8;
                const int h = (o & 1023) >> 6;
                const int d = o & 63;
                size_t base = ((size_t)(bb * Hn + h) * Nseq + n) * Dh + d;
                *(uint32_t*)(dstb + base)          = packh2(acc[mb][nb][0] * sc,
                                                            acc[mb][nb][1] * sc);
                *(uint32_t*)(dstb + base + 8 * Dh) = packh2(acc[mb][nb][2] * sc,
                                                            acc[mb][nb][3] * sc);
            }
        }
    } else {
#pragma unroll
        for (int mb = 0; mb < 4; mb++) {
            const int m = erow + mb * 16;
#pragma unroll
            for (int nb = 0; nb < 4; nb++) {
                const int o = ecol + nb * 8;
                const float2 bv = *(const float2*)(bias + o);
                float* dst = out + (size_t)m * Cdim + o;
                *(float2*)dst = make_float2(acc[mb][nb][0] + bv.x,
                                            acc[mb][nb][1] + bv.y);
                *(float2*)(dst + 8 * Cdim) = make_float2(acc[mb][nb][2] + bv.x,
                                                         acc[mb][nb][3] + bv.y);
            }
        }
    }
}

// ---------------------------------------------------------------------------
// Flash attention, single fp16: S = Q*K^T, O += P*V.
// CTA: 128 Q rows x one (b,h), 8 warps. KV in 64-row tiles, 3-stage ring,
// refill at chunk TOP (stage (kb+2)%3 = (kb-1)%3 — reads done before this
// chunk's barrier), no trailing barrier. smem 74KB -> 2 CTAs/SM.
// ---------------------------------------------------------------------------
#define APITCH 144
#define AQREG  (128 * APITCH)            // 18432 (one Q matrix)
#define AKREG  (64 * APITCH)             // 9216 per KV matrix
#define AKV0   AQREG
#define ASTAGE (2 * AKREG)               // K, V = 18432
#define ANST   3
#define ATTN_SMEM (AQREG + ANST * ASTAGE)   // 73728

__global__ __launch_bounds__(256, 2) void attn_f16() {
    extern __shared__ char smem[];
    const uint32_t sb = s2u(smem);
    const int tid = threadIdx.x;
    const int w = tid >> 5, lane = tid & 31;
    const int bh = blockIdx.x;
    const int qb = blockIdx.y;

    const size_t hoff = (size_t)bh * (Nseq * Dh);
    const __half* qp = g_q + hoff + (size_t)qb * 128 * Dh;

    auto loadQ = [&]() {
#pragma unroll
        for (int j = 0; j < 4; j++) {
            int idx = j * 256 + tid;          // 0..1023
            int r   = (idx >> 3) & 127;
            int c8  = idx & 7;
            cpa16(sb + r * APITCH + c8 * 16, qp + r * Dh + c8 * 8);
        }
    };
    auto loadKV = [&](int kb, int st) {     // kb: 64-row block 0..15
        const size_t koff = hoff + (size_t)kb * 64 * Dh;
        const __half* srcs[2] = {g_k + koff, g_v + koff};
        uint32_t base = sb + AKV0 + st * ASTAGE;
#pragma unroll
        for (int j = 0; j < 4; j++) {
            int idx = j * 256 + tid;          // 0..1023
            int mt  = idx >> 9;               // 0=K 1=V
            int r   = (idx >> 3) & 63;
            int c8  = idx & 7;
            cpa16(base + mt * AKREG + r * APITCH + c8 * 16,
                  srcs[mt] + r * Dh + c8 * 8);
        }
    };

    loadQ();          CP_COMMIT;   // g0: Q
    loadKV(0, 0);     CP_COMMIT;   // g1: KV0
    loadKV(1, 1);     CP_COMMIT;   // g2: KV1

    const int a_rowb = (w * 16 + (lane & 15)) * APITCH + (lane >> 4) * 16;
    const int k_rowi = ((lane >> 4) << 3) + (lane & 7);
    const int k_colb = ((lane >> 3) & 1) * 16;
    const int v_rowi = (lane & 7) + ((lane >> 3) & 1) * 8;
    const int v_colb = (lane >> 4) * 16;

    CP_WAIT(2);       // Q resident
    __syncthreads();

    uint32_t QA[4][4];
#pragma unroll
    for (int kc = 0; kc < 4; kc++)
        ldsm4(QA[kc], sb + a_rowb + kc * 32);

    float O[8][4];
#pragma unroll
    for (int i = 0; i < 8; i++)
#pragma unroll
        for (int j = 0; j < 4; j++) O[i][j] = 0.0f;
    float m0 = -1e30f, m1 = -1e30f;
    float l0 = 0.0f, l1 = 0.0f;

    for (int kb = 0; kb < 16; kb++) {
        if (kb + 1 < 16) { CP_WAIT(1); } else { CP_WAIT(0); }
        __syncthreads();
        // refill at TOP: stage (kb+2)%3 = (kb-1)%3, reads finished before the
        // barrier above -> copy gets ~2 chunks to land; no trailing barrier.
        if (kb + 2 < 16) { loadKV(kb + 2, (kb + 2) % ANST); CP_COMMIT; }

        const uint32_t kbase = sb + AKV0 + (kb % ANST) * ASTAGE;

        float S[8][4];
#pragma unroll
        for (int i = 0; i < 8; i++)
#pragma unroll
            for (int j = 0; j < 4; j++) S[i][j] = 0.0f;

#pragma unroll
        for (int ng = 0; ng < 4; ng++) {
#pragma unroll
            for (int kc = 0; kc < 4; kc++) {
                uint32_t kf[4];
                ldsm4(kf, kbase + (ng * 16 + k_rowi) * APITCH + k_colb + kc * 32);
#pragma unroll
                for (int half = 0; half < 2; half++)
                    mma16816h(S[ng * 2 + half], QA[kc], &kf[half * 2]);
            }
        }

        float rm0 = -1e30f, rm1 = -1e30f;
#pragma unroll
        for (int i = 0; i < 8; i++) {
            rm0 = fmaxf(rm0, fmaxf(S[i][0], S[i][1]));
            rm1 = fmaxf(rm1, fmaxf(S[i][2], S[i][3]));
        }
        rm0 = fmaxf(rm0, __shfl_xor_sync(0xffffffffu, rm0, 1));
        rm0 = fmaxf(rm0, __shfl_xor_sync(0xffffffffu, rm0, 2));
        rm1 = fmaxf(rm1, __shfl_xor_sync(0xffffffffu, rm1, 1));
        rm1 = fmaxf(rm1, __shfl_xor_sync(0xffffffffu, rm1, 2));

        float mn0 = fmaxf(m0, rm0), mn1 = fmaxf(m1, rm1);
        float al0 = ex2(m0 - mn0),  al1 = ex2(m1 - mn1);
        m0 = mn0; m1 = mn1;
        l0 *= al0; l1 *= al1;
#pragma unroll
        for (int i = 0; i < 8; i++) {
            O[i][0] *= al0; O[i][1] *= al0;
            O[i][2] *= al1; O[i][3] *= al1;
        }
        float ps0 = 0.0f, ps1 = 0.0f;
#pragma unroll
        for (int i = 0; i < 8; i++) {
            S[i][0] = ex2(S[i][0] - mn0);
            S[i][1] = ex2(S[i][1] - mn0);
            S[i][2] = ex2(S[i][2] - mn1);
            S[i][3] = ex2(S[i][3] - mn1);
            ps0 += S[i][0] + S[i][1];
            ps1 += S[i][2] + S[i][3];
        }
        l0 += ps0; l1 += ps1;

#pragma unroll
        for (int kc2 = 0; kc2 < 4; kc2++) {
            uint32_t pf[4];
            pf[0] = packh2(S[2 * kc2][0],     S[2 * kc2][1]);
            pf[1] = packh2(S[2 * kc2][2],     S[2 * kc2][3]);
            pf[2] = packh2(S[2 * kc2 + 1][0], S[2 * kc2 + 1][1]);
            pf[3] = packh2(S[2 * kc2 + 1][2], S[2 * kc2 + 1][3]);
#pragma unroll
            for (int dg = 0; dg < 4; dg++) {
                uint32_t vf[4];
                ldsm4t(vf, kbase + AKREG
                           + (kc2 * 16 + v_rowi) * APITCH + v_colb + dg * 32);
#pragma unroll
                for (int half = 0; half < 2; half++)
                    mma16816h(O[dg * 2 + half], pf, &vf[half * 2]);
            }
        }
    }

    l0 += __shfl_xor_sync(0xffffffffu, l0, 1);
    l0 += __shfl_xor_sync(0xffffffffu, l0, 2);
    l1 += __shfl_xor_sync(0xffffffffu, l1, 1);
    l1 += __shfl_xor_sync(0xffffffffu, l1, 2);
    const float inv0 = 1.0f / l0, inv1 = 1.0f / l1;

    const int b = bh >> 4, h = bh & 15;
    const int n0 = qb * 128 + w * 16 + (lane >> 2);
#pragma unroll
    for (int nb = 0; nb < 8; nb++) {
        const int d = nb * 8 + (lane & 3) * 2;
        size_t base0 = ((size_t)(b * Nseq + n0) * Cdim) + h * Dh + d;
        size_t base1 = base0 + (size_t)8 * Cdim;
        *(uint32_t*)(g_ao + base0) = packh2(O[nb][0] * inv0, O[nb][1] * inv0);
        *(uint32_t*)(g_ao + base1) = packh2(O[nb][2] * inv1, O[nb][3] * inv1);
    }
}

// ---------------------------------------------------------------------------
extern "C" void kernel_launch(void* const* d_in, const int* in_sizes, int n_in,
                              void* d_out, int out_size) {
    const float* x      = (const float*)d_in[0];   // [8,1024,1024]
    const float* w_qkv  = (const float*)d_in[1];   // [3072,1024]
    const float* w_proj = (const float*)d_in[2];   // [1024,1024]
    const float* b_proj = (const float*)d_in[3];   // [1024]
    float* out = (float*)d_out;

    cudaFuncSetAttribute(gemm_f16,
                         cudaFuncAttributeMaxDynamicSharedMemorySize, GEMM_SMEM);
    cudaFuncSetAttribute(attn_f16,
                         cudaFuncAttributeMaxDynamicSharedMemorySize, ATTN_SMEM);

    {
        int n4 = X4 + WQ4 + WP4;
        cvt_all<<<(n4 + 255) / 256, 256>>>((const float4*)x,
                                           (const float4*)w_qkv,
                                           (const float4*)w_proj);
    }

    dim3 g1(OQKV / 128, Mrows / 128);              // (24, 64)
    gemm_f16<<<g1, 256, GEMM_SMEM>>>(0, nullptr, nullptr);

    dim3 g2(Bsz * Hn, Nseq / 128);                 // (128, 8)
    attn_f16<<<g2, 256, ATTN_SMEM>>>();

    dim3 g3(Cdim / 128, Mrows / 128);              // (8, 64)
    gemm_f16<<<g3, 256, GEMM_SMEM>>>(1, b_proj, out);
}